// round 7
// baseline (speedup 1.0000x reference)
#include <cuda_runtime.h>
#include <cuda_fp16.h>
#include <cstdint>

#define NTOT   262144
#define NTILES 4096                     // 64 n per tile
#define SCALE  0.14433756729740643f

// smem offsets (from 1KB-aligned base)
#define OFF_A   0                       // 256 rows x 120 fp16 (240B): [0..54]=xh,55=0,[56..110]=xl,pad
#define OFF_B   61440                   // 112 x 184 fp16 (368B): [0..55]=wh,[56..111]=wh,[112..167]=wl,pad
#define OFF_T   102656                  // 256 rows x 58 f32
#define OFF_XP  162048                  // 256 rows x 60 f32 (OS aliases)
#define OFF_OS  OFF_XP                  // 64 n x 224 f32 = 57344B
#define OFF_AT  223488                  // 256 x 4 f32 probs
#define SMEM_USED 227584
#define SMEM_TOTAL (SMEM_USED + 1024)

__device__ unsigned short g_B[112 * 184];

__global__ void prep_kernel(const float* __restrict__ wq, const float* __restrict__ wk,
                            const float* __restrict__ wv, const float* __restrict__ wfc) {
    int idx = blockIdx.x * blockDim.x + threadIdx.x;
    if (idx >= 112 * 184) return;
    int j = idx / 184;
    int k = idx - j * 184;
    int sec = (k < 56) ? 0 : (k < 112) ? 1 : (k < 168) ? 2 : 3;
    float w = 0.f;
    if (sec < 3) {
        int d = k - sec * 56;
        if (d < 55) {
            if (j < 55) {
                float s = 0.f;
                #pragma unroll 8
                for (int e = 0; e < 48; e++) s += wq[e * 55 + d] * wk[e * 55 + j];
                w = s * SCALE;
            } else if (j >= 56 && j < 111) {
                int dd = j - 56;
                float s = 0.f;
                #pragma unroll 8
                for (int e = 0; e < 48; e++) s += wv[e * 55 + d] * wfc[dd * 48 + e];
                w = s;
            }
        }
    }
    __half wh = __float2half_rn(w);
    __half o;
    if (sec == 2)      o = __float2half_rn(w - __half2float(wh));
    else if (sec == 3) o = __float2half_rn(0.f);
    else               o = wh;
    g_B[idx] = __half_as_ushort(o);
}

__device__ __forceinline__ uint32_t s2u(const void* p) {
    uint32_t a;
    asm("{ .reg .u64 t; cvta.to.shared.u64 t, %1; cvt.u32.u64 %0, t; }" : "=r"(a) : "l"(p));
    return a;
}
__device__ __forceinline__ void ldsm4(uint32_t* r, uint32_t addr) {
    asm volatile("ldmatrix.sync.aligned.m8n8.x4.shared.b16 {%0,%1,%2,%3}, [%4];"
                 : "=r"(r[0]), "=r"(r[1]), "=r"(r[2]), "=r"(r[3]) : "r"(addr));
}
__device__ __forceinline__ void mma16816(float* c, const uint32_t* a, uint32_t b0, uint32_t b1) {
    asm volatile("mma.sync.aligned.m16n8k16.row.col.f32.f16.f16.f32 "
                 "{%0,%1,%2,%3}, {%4,%5,%6,%7}, {%8,%9}, {%0,%1,%2,%3};"
                 : "+f"(c[0]), "+f"(c[1]), "+f"(c[2]), "+f"(c[3])
                 : "r"(a[0]), "r"(a[1]), "r"(a[2]), "r"(a[3]), "r"(b0), "r"(b1));
}

__global__ __launch_bounds__(256, 1) void mha_kernel(const float* __restrict__ x,
                                                     const float* __restrict__ bfc,
                                                     float* __restrict__ out) {
    extern __shared__ char smraw[];
    uint32_t sb0 = s2u(smraw);
    uint32_t sb  = (sb0 + 1023u) & ~1023u;
    char* sm = smraw + (sb - sb0);

    const int tid  = threadIdx.x;
    const int wid  = tid >> 5;
    const int lane = tid & 31;

    // one-time init
    for (int i = tid; i < 112 * 184; i += 256)
        ((unsigned short*)(sm + OFF_B))[i] = g_B[i];
    for (int i = tid; i < 61440 / 4; i += 256)
        *(uint32_t*)(sm + OFF_A + i * 4) = 0u;
    __syncthreads();

    const int gid = lane >> 2, tig = lane & 3;
    const int town = gid & 3;                       // owned t-position
    const int R0  = wid * 32;
    const uint32_t aBase = sb + OFF_A + (uint32_t)(R0 + (lane & 15)) * 240
                         + (uint32_t)((lane >> 4) & 1) * 16;
    const int jb   = (lane & 7) + ((lane >> 4) & 1) * 8;
    const int kadd = ((lane >> 3) & 1) * 16;

    // epilogue constants per thread (depend on tig / town)
    int   dcol[14];
    dcol[0] = 2 * tig; dcol[1] = 2 * tig + 1;
    #pragma unroll
    for (int g = 0; g < 3; g++) {
        int base = 8 + 16 * g + 2 * tig;
        dcol[2 + 4 * g] = base;     dcol[3 + 4 * g] = base + 1;
        dcol[4 + 4 * g] = base + 8; dcol[5 + 4 * g] = base + 9;
    }
    float biasv[14];
    int   posD[14];
    #pragma unroll
    for (int u = 0; u < 14; u++) {
        int d = dcol[u];
        biasv[u] = (d < 55) ? bfc[d] : 0.f;
        int dc = (d < 55) ? d : 0;
        posD[u] = (dc / 5) * 10 + (dc % 5);
    }
    const int posS = (town >> 1) * 110 + (town & 1) * 5;

    float* T  = (float*)(sm + OFF_T);
    float* XP = (float*)(sm + OFF_XP);
    float* OS = (float*)(sm + OFF_OS);
    float* AT = (float*)(sm + OFF_AT);

    for (int t = blockIdx.x; t < NTILES; t += gridDim.x) {
        // ---- scatter: gmem -> A (fp16 hi/lo) + XP (f32), (row=(n,s), d) ----
        {
            const float4* xin = (const float4*)(x + (size_t)t * 14080);
            #pragma unroll
            for (int i = 0; i < 14; i++) {
                int idx = tid + 256 * i;
                if (idx < 3520) {
                    float4 v = xin[idx];
                    float vv[4] = {v.x, v.y, v.z, v.w};
                    int n_l = idx / 55;
                    int l0  = (idx - n_l * 55) * 4;
                    #pragma unroll
                    for (int jj = 0; jj < 4; jj++) {
                        int l  = l0 + jj;
                        int r  = l / 10, cc = l - r * 10;
                        int p1 = r / 11, h = r - p1 * 11;
                        int p2 = cc / 5, w = cc - p2 * 5;
                        int row = n_l * 4 + p1 * 2 + p2;
                        int d   = h * 5 + w;
                        float val = vv[jj];
                        XP[row * 60 + d] = val;
                        __half hh = __float2half_rn(val);
                        __half hl = __float2half_rn(val - __half2float(hh));
                        *(__half*)(sm + OFF_A + row * 240 + d * 2)         = hh;
                        *(__half*)(sm + OFF_A + row * 240 + (56 + d) * 2)  = hl;
                    }
                }
            }
            XP[tid * 60 + 55] = 0.f;      // re-zero pad col (OS alias clobbers)
        }
        __syncthreads();

        // ---- MMA: 2 m-tiles/warp, 7 n-strips, 7+4 ksteps; T->smem, U->regs ----
        float Ureg[4][14];
        {
            uint32_t aF[2][7][4];
            #pragma unroll
            for (int mt = 0; mt < 2; mt++)
                #pragma unroll
                for (int ks = 0; ks < 7; ks++)
                    ldsm4(aF[mt][ks], aBase + (uint32_t)mt * 3840 + ks * 32);

            #pragma unroll
            for (int ntp = 0; ntp < 7; ntp++) {
                float acc[2][8];
                #pragma unroll
                for (int mt = 0; mt < 2; mt++)
                    #pragma unroll
                    for (int q = 0; q < 8; q++) acc[mt][q] = 0.f;

                uint32_t bbase = sb + OFF_B + (uint32_t)(ntp * 16 + jb) * 368 + kadd;
                #pragma unroll
                for (int ks = 0; ks < 7; ks++) {
                    uint32_t bf[4];
                    ldsm4(bf, bbase + ks * 32);
                    #pragma unroll
                    for (int mt = 0; mt < 2; mt++) {
                        mma16816(acc[mt],     aF[mt][ks], bf[0], bf[1]);
                        mma16816(acc[mt] + 4, aF[mt][ks], bf[2], bf[3]);
                    }
                }
                #pragma unroll
                for (int ks = 0; ks < 4; ks++) {
                    uint32_t bf[4];
                    ldsm4(bf, bbase + 224 + ks * 32);
                    #pragma unroll
                    for (int mt = 0; mt < 2; mt++) {
                        mma16816(acc[mt],     aF[mt][ks], bf[0], bf[1]);
                        mma16816(acc[mt] + 4, aF[mt][ks], bf[2], bf[3]);
                    }
                }

                int c0 = ntp * 16 + 2 * tig;
                #pragma unroll
                for (int mt = 0; mt < 2; mt++) {
                    int r = R0 + mt * 16 + gid;
                    if (ntp <= 3) {
                        *(float2*)(T + r * 58 + c0)       = make_float2(acc[mt][0], acc[mt][1]);
                        *(float2*)(T + (r + 8) * 58 + c0) = make_float2(acc[mt][2], acc[mt][3]);
                    }
                    if (ntp <= 2) {
                        *(float2*)(T + r * 58 + c0 + 8)       = make_float2(acc[mt][4], acc[mt][5]);
                        *(float2*)(T + (r + 8) * 58 + c0 + 8) = make_float2(acc[mt][6], acc[mt][7]);
                    }
                    if (ntp == 3) {
                        Ureg[mt * 2][0]     = acc[mt][4]; Ureg[mt * 2][1]     = acc[mt][5];
                        Ureg[mt * 2 + 1][0] = acc[mt][6]; Ureg[mt * 2 + 1][1] = acc[mt][7];
                    }
                    if (ntp >= 4) {
                        int u0 = 2 + (ntp - 4) * 4;
                        Ureg[mt * 2][u0]         = acc[mt][0]; Ureg[mt * 2][u0 + 1]     = acc[mt][1];
                        Ureg[mt * 2 + 1][u0]     = acc[mt][2]; Ureg[mt * 2 + 1][u0 + 1] = acc[mt][3];
                        Ureg[mt * 2][u0 + 2]     = acc[mt][4]; Ureg[mt * 2][u0 + 3]     = acc[mt][5];
                        Ureg[mt * 2 + 1][u0 + 2] = acc[mt][6]; Ureg[mt * 2 + 1][u0 + 3] = acc[mt][7];
                    }
                }
            }
        }
        __syncthreads();

        // ---- stage C: thread=(n,s): S[s][t] = T[n,s] . x[n,t]; local softmax ----
        {
            int nl = tid >> 2, sq = tid & 3;
            const float* tr = T + (nl * 4 + sq) * 58;
            float sv[4] = {0.f, 0.f, 0.f, 0.f};
            #pragma unroll
            for (int i = 0; i < 14; i++) {
                float2 ta = *(const float2*)(tr + 4 * i);
                float2 tb = *(const float2*)(tr + 4 * i + 2);
                #pragma unroll
                for (int tt = 0; tt < 4; tt++) {
                    float4 xv = *(const float4*)(XP + (nl * 4 + tt) * 60 + 4 * i);
                    sv[tt] += ta.x * xv.x + ta.y * xv.y + tb.x * xv.z + tb.y * xv.w;
                }
            }
            float m = fmaxf(fmaxf(sv[0], sv[1]), fmaxf(sv[2], sv[3]));
            float e0 = __expf(sv[0] - m), e1 = __expf(sv[1] - m);
            float e2 = __expf(sv[2] - m), e3 = __expf(sv[3] - m);
            float inv = 1.f / (e0 + e1 + e2 + e3);
            *(float4*)(AT + tid * 4) = make_float4(e0 * inv, e1 * inv, e2 * inv, e3 * inv);
        }
        __syncthreads();

        // ---- stage D: out = b + p·U via 3-shfl butterfly over t (lane bits 2,3) ----
        #pragma unroll
        for (int rp = 0; rp < 4; rp++) {
            int row = R0 + (rp >> 1) * 16 + gid + 8 * (rp & 1);
            int nt  = row >> 2;
            int ab  = (nt * 4 + town) * 4;
            float q0 = AT[ab + town];
            float q1 = AT[ab + (town ^ 1)];
            float q2 = AT[ab + (town ^ 2)];
            float q3 = AT[ab + (town ^ 3)];
            float* os = OS + nt * 224 + posS;
            #pragma unroll
            for (int u = 0; u < 14; u++) {
                float own = Ureg[rp][u];
                float ua = __shfl_xor_sync(0xffffffffu, own, 4);
                float ub = __shfl_xor_sync(0xffffffffu, own, 8);
                float uc = __shfl_xor_sync(0xffffffffu, own, 12);
                float o = biasv[u] + q0 * own + q1 * ua + q2 * ub + q3 * uc;
                if (dcol[u] < 55) os[posD[u]] = o;
            }
        }
        __syncthreads();

        // ---- coalesced store OS -> gmem ----
        {
            float* gout = out + (size_t)t * 14080;
            #pragma unroll
            for (int i = 0; i < 14; i++) {
                int idx = tid + 256 * i;
                if (idx < 3520) {
                    int n = idx / 55, jj = idx - n * 55;
                    *(float4*)(gout + n * 220 + jj * 4) =
                        *(const float4*)(OS + n * 224 + jj * 4);
                }
            }
        }
        __syncthreads();
    }
}

extern "C" void kernel_launch(void* const* d_in, const int* in_sizes, int n_in,
                              void* d_out, int out_size) {
    const float* x   = (const float*)d_in[0];
    const float* wq  = (const float*)d_in[1];
    const float* wk  = (const float*)d_in[2];
    const float* wv  = (const float*)d_in[3];
    const float* wfc = (const float*)d_in[4];
    const float* bfc = (const float*)d_in[5];
    float* out = (float*)d_out;

    int nsm = 148;
    cudaDeviceGetAttribute(&nsm, cudaDevAttrMultiProcessorCount, 0);

    cudaFuncSetAttribute(mha_kernel, cudaFuncAttributeMaxDynamicSharedMemorySize, SMEM_TOTAL);
    prep_kernel<<<(112 * 184 + 255) / 256, 256>>>(wq, wk, wv, wfc);
    mha_kernel<<<nsm, 256, SMEM_TOTAL>>>(x, bfc, out);
}

// round 8
// speedup vs baseline: 1.1184x; 1.1184x over previous
#include <cuda_runtime.h>
#include <cuda_fp16.h>
#include <cstdint>

#define NTOT   262144
#define NTILES 16384                    // 16 n per tile
#define SCALE  0.14433756729740643f

// smem (from 1KB-aligned base)
#define OFF_A   0                       // 64 rows x 272B fp16: bytes [0,128)=xh(k0..63), [128,256)=xl
#define OFF_XP  17408                   // 64 x 60 f32 (OS aliases)
#define OFF_OS  OFF_XP                  // 16 n x 224 f32 = 14336 <= 15360
#define OFF_T   32768                   // 64 x 60 f32
#define OFF_AT  48128                   // 16 n x 16 f32
#define SMEM_USED 49152
#define SMEM_TOTAL (SMEM_USED + 1024)

// B in mma-fragment order: [strip(7)][kstep(8: 4 wh + 4 wl)][lane(32)] -> uint4
__device__ uint4 g_Bfrag[7 * 8 * 32];

__device__ __forceinline__ float foldw(int j, int k,
                                       const float* wq, const float* wk,
                                       const float* wv, const float* wfc) {
    if (k >= 55) return 0.f;
    if (j < 55) {
        float s = 0.f;
        #pragma unroll 8
        for (int e = 0; e < 48; e++) s += wq[e * 55 + k] * wk[e * 55 + j];
        return s * SCALE;
    }
    if (j >= 56 && j < 111) {
        int dd = j - 56;
        float s = 0.f;
        #pragma unroll 8
        for (int e = 0; e < 48; e++) s += wv[e * 55 + k] * wfc[dd * 48 + e];
        return s;
    }
    return 0.f;
}
__device__ __forceinline__ uint32_t pack2(float w0, float w1, bool lo) {
    __half h0 = __float2half_rn(w0), h1 = __float2half_rn(w1);
    __half o0 = lo ? __float2half_rn(w0 - __half2float(h0)) : h0;
    __half o1 = lo ? __float2half_rn(w1 - __half2float(h1)) : h1;
    return (uint32_t)__half_as_ushort(o0) | ((uint32_t)__half_as_ushort(o1) << 16);
}

__global__ void prep_kernel(const float* __restrict__ wq, const float* __restrict__ wk,
                            const float* __restrict__ wv, const float* __restrict__ wfc) {
    int idx = blockIdx.x * 256 + threadIdx.x;
    if (idx >= 1792) return;
    int lane  = idx & 31;
    int ks    = (idx >> 5) & 7;
    int strip = idx >> 8;
    bool lo   = ks >= 4;
    int kb    = (lo ? ks - 4 : ks) * 16 + 2 * (lane & 3);
    int r     = strip * 16 + (lane >> 2);
    uint4 v;
    v.x = pack2(foldw(r,     kb,     wq,wk,wv,wfc), foldw(r,     kb + 1, wq,wk,wv,wfc), lo);
    v.y = pack2(foldw(r,     kb + 8, wq,wk,wv,wfc), foldw(r,     kb + 9, wq,wk,wv,wfc), lo);
    v.z = pack2(foldw(r + 8, kb,     wq,wk,wv,wfc), foldw(r + 8, kb + 1, wq,wk,wv,wfc), lo);
    v.w = pack2(foldw(r + 8, kb + 8, wq,wk,wv,wfc), foldw(r + 8, kb + 9, wq,wk,wv,wfc), lo);
    g_Bfrag[idx] = v;
}

__device__ __forceinline__ uint32_t s2u(const void* p) {
    uint32_t a;
    asm("{ .reg .u64 t; cvta.to.shared.u64 t, %1; cvt.u32.u64 %0, t; }" : "=r"(a) : "l"(p));
    return a;
}
__device__ __forceinline__ void ldsm4(uint32_t* r, uint32_t addr) {
    asm volatile("ldmatrix.sync.aligned.m8n8.x4.shared.b16 {%0,%1,%2,%3}, [%4];"
                 : "=r"(r[0]), "=r"(r[1]), "=r"(r[2]), "=r"(r[3]) : "r"(addr));
}
__device__ __forceinline__ void mma16816(float* c, const uint32_t* a, uint32_t b0, uint32_t b1) {
    asm volatile("mma.sync.aligned.m16n8k16.row.col.f32.f16.f16.f32 "
                 "{%0,%1,%2,%3}, {%4,%5,%6,%7}, {%8,%9}, {%0,%1,%2,%3};"
                 : "+f"(c[0]), "+f"(c[1]), "+f"(c[2]), "+f"(c[3])
                 : "r"(a[0]), "r"(a[1]), "r"(a[2]), "r"(a[3]), "r"(b0), "r"(b1));
}

__global__ __launch_bounds__(128, 4) void mha_kernel(const float* __restrict__ x,
                                                     const float* __restrict__ bfc,
                                                     float* __restrict__ out) {
    extern __shared__ char smraw[];
    uint32_t sb0 = s2u(smraw);
    uint32_t sb  = (sb0 + 1023u) & ~1023u;
    char* sm = smraw + (sb - sb0);

    const int tid  = threadIdx.x;
    const int wid  = tid >> 5;
    const int lane = tid & 31;

    // zero A once (row pads persist)
    for (int i = tid; i < 17408 / 4; i += 128)
        *(uint32_t*)(sm + OFF_A + i * 4) = 0u;

    const int gid = lane >> 2, tig = lane & 3;
    const int town = gid & 3;
    const int R0  = wid * 16;
    const uint32_t aBase = sb + OFF_A + (uint32_t)(R0 + (lane & 15)) * 272
                         + (uint32_t)((lane >> 4) & 1) * 16;

    // epilogue constants
    int   dcol0 = 2 * tig;
    float biasv[14];
    int   posD[14];
    {
        int dcols[14];
        dcols[0] = dcol0; dcols[1] = dcol0 + 1;
        #pragma unroll
        for (int g = 0; g < 3; g++) {
            int base = 8 + 16 * g + 2 * tig;
            dcols[2 + 4 * g] = base;     dcols[3 + 4 * g] = base + 1;
            dcols[4 + 4 * g] = base + 8; dcols[5 + 4 * g] = base + 9;
        }
        #pragma unroll
        for (int u = 0; u < 14; u++) {
            int d = dcols[u];
            biasv[u] = (d < 55) ? bfc[d] : 0.f;
            int dc = (d < 55) ? d : 0;
            posD[u] = (dc / 5) * 10 + (dc % 5);
        }
    }
    const int posS = (town >> 1) * 110 + (town & 1) * 5;

    float* T  = (float*)(sm + OFF_T);
    float* XP = (float*)(sm + OFF_XP);
    float* OS = (float*)(sm + OFF_OS);
    float* AT = (float*)(sm + OFF_AT);
    const uint4* gb0 = g_Bfrag + lane;
    __syncthreads();

    for (int t = blockIdx.x; t < NTILES; t += gridDim.x) {
        // ---- scatter: gmem -> A (xh|xl fp16) + XP (f32) ----
        {
            const float4* xin = (const float4*)(x + (size_t)t * 3520);
            #pragma unroll
            for (int i = 0; i < 7; i++) {
                int idx = tid + 128 * i;
                if (idx < 880) {
                    float4 v = xin[idx];
                    float vv[4] = {v.x, v.y, v.z, v.w};
                    int n_l = idx / 55;
                    int l0  = (idx - n_l * 55) * 4;
                    #pragma unroll
                    for (int jj = 0; jj < 4; jj++) {
                        int l  = l0 + jj;
                        int r  = l / 10, cc = l - r * 10;
                        int p1 = r / 11, h = r - p1 * 11;
                        int p2 = cc / 5, w = cc - p2 * 5;
                        int row = n_l * 4 + p1 * 2 + p2;
                        int d   = h * 5 + w;
                        float val = vv[jj];
                        XP[row * 60 + d] = val;
                        __half hh = __float2half_rn(val);
                        __half hl = __float2half_rn(val - __half2float(hh));
                        *(__half*)(sm + OFF_A + row * 272 + d * 2)        = hh;
                        *(__half*)(sm + OFF_A + row * 272 + 128 + d * 2)  = hl;
                    }
                }
            }
            if (tid < 64) XP[tid * 60 + 55] = 0.f;   // re-zero pad col (OS alias)
        }
        __syncthreads();

        // ---- MMA: 7 strips x (4 wh x {xh,xl} + 4 wl x xh); T->smem, U->regs ----
        float Ureg[2][14];
        {
            uint32_t aFh[4][4], aFl[4][4];
            #pragma unroll
            for (int ks = 0; ks < 4; ks++) {
                ldsm4(aFh[ks], aBase + ks * 32);
                ldsm4(aFl[ks], aBase + 128 + ks * 32);
            }
            #pragma unroll
            for (int ntp = 0; ntp < 7; ntp++) {
                float acc[8];
                #pragma unroll
                for (int q = 0; q < 8; q++) acc[q] = 0.f;
                const uint4* gb = gb0 + ntp * 256;
                #pragma unroll
                for (int ks = 0; ks < 4; ks++) {            // wh x (xh + xl)
                    uint4 bf = __ldg(gb + ks * 32);
                    mma16816(acc,     aFh[ks], bf.x, bf.y);
                    mma16816(acc + 4, aFh[ks], bf.z, bf.w);
                    mma16816(acc,     aFl[ks], bf.x, bf.y);
                    mma16816(acc + 4, aFl[ks], bf.z, bf.w);
                }
                #pragma unroll
                for (int ks = 0; ks < 4; ks++) {            // wl x xh
                    uint4 bf = __ldg(gb + (4 + ks) * 32);
                    mma16816(acc,     aFh[ks], bf.x, bf.y);
                    mma16816(acc + 4, aFh[ks], bf.z, bf.w);
                }
                int c0 = ntp * 16 + 2 * tig;
                int r  = R0 + gid;
                if (ntp <= 3) {
                    *(float2*)(T + r * 60 + c0)       = make_float2(acc[0], acc[1]);
                    *(float2*)(T + (r + 8) * 60 + c0) = make_float2(acc[2], acc[3]);
                }
                if (ntp <= 2) {
                    *(float2*)(T + r * 60 + c0 + 8)       = make_float2(acc[4], acc[5]);
                    *(float2*)(T + (r + 8) * 60 + c0 + 8) = make_float2(acc[6], acc[7]);
                }
                if (ntp == 3) {
                    Ureg[0][0] = acc[4]; Ureg[0][1] = acc[5];
                    Ureg[1][0] = acc[6]; Ureg[1][1] = acc[7];
                }
                if (ntp >= 4) {
                    int u0 = 2 + (ntp - 4) * 4;
                    Ureg[0][u0]     = acc[0]; Ureg[0][u0 + 1] = acc[1];
                    Ureg[1][u0]     = acc[2]; Ureg[1][u0 + 1] = acc[3];
                    Ureg[0][u0 + 2] = acc[4]; Ureg[0][u0 + 3] = acc[5];
                    Ureg[1][u0 + 2] = acc[6]; Ureg[1][u0 + 3] = acc[7];
                }
            }
        }
        __syncthreads();

        // ---- stage C: S = T x^T + softmax (128 thr = 16n x 4s x 2tp) ----
        {
            int nl = tid >> 3;
            int s4 = (tid >> 1) & 3;
            int tp = tid & 1;
            const float4* tr = (const float4*)(T + (nl * 4 + s4) * 60);
            const float4* x0 = (const float4*)(XP + (nl * 4 + 2 * tp) * 60);
            const float4* x1 = (const float4*)(XP + (nl * 4 + 2 * tp + 1) * 60);
            float sv0 = 0.f, sv1 = 0.f;
            #pragma unroll
            for (int i = 0; i < 14; i++) {
                float4 tv = tr[i], a = x0[i], b = x1[i];
                sv0 += tv.x * a.x + tv.y * a.y + tv.z * a.z + tv.w * a.w;
                sv1 += tv.x * b.x + tv.y * b.y + tv.z * b.z + tv.w * b.w;
            }
            float o0 = __shfl_xor_sync(0xffffffffu, sv0, 1);
            float o1 = __shfl_xor_sync(0xffffffffu, sv1, 1);
            float t0, t1, t2, t3;
            if (tp == 0) { t0 = sv0; t1 = sv1; t2 = o0; t3 = o1; }
            else         { t0 = o0;  t1 = o1;  t2 = sv0; t3 = sv1; }
            float m = fmaxf(fmaxf(t0, t1), fmaxf(t2, t3));
            float e0 = __expf(t0 - m), e1 = __expf(t1 - m);
            float e2 = __expf(t2 - m), e3 = __expf(t3 - m);
            float inv = 1.f / (e0 + e1 + e2 + e3);
            if (tp == 0)
                *(float4*)(AT + (nl * 4 + s4) * 4) =
                    make_float4(e0 * inv, e1 * inv, e2 * inv, e3 * inv);
        }
        __syncthreads();

        // ---- stage D: out = b + p*U via shfl butterfly over t (lane bits 2,3) ----
        #pragma unroll
        for (int rp = 0; rp < 2; rp++) {
            int row = R0 + gid + 8 * rp;
            int nt  = row >> 2;
            int ab  = (nt * 4 + town) * 4;
            float q0 = AT[ab + town];
            float q1 = AT[ab + (town ^ 1)];
            float q2 = AT[ab + (town ^ 2)];
            float q3 = AT[ab + (town ^ 3)];
            float* os = OS + nt * 224 + posS;
            #pragma unroll
            for (int u = 0; u < 14; u++) {
                float own = Ureg[rp][u];
                float ua = __shfl_xor_sync(0xffffffffu, own, 4);
                float ub = __shfl_xor_sync(0xffffffffu, own, 8);
                float uc = __shfl_xor_sync(0xffffffffu, own, 12);
                float o = biasv[u] + q0 * own + q1 * ua + q2 * ub + q3 * uc;
                if (u != 13 || tig != 3)            // only dcol==55 case excluded
                    os[posD[u]] = o;
            }
        }
        __syncthreads();

        // ---- coalesced store OS -> gmem ----
        {
            float* gout = out + (size_t)t * 3520;
            #pragma unroll
            for (int i = 0; i < 7; i++) {
                int idx = tid + 128 * i;
                if (idx < 880) {
                    int n = idx / 55, jj = idx - n * 55;
                    *(float4*)(gout + n * 220 + jj * 4) =
                        *(const float4*)(OS + n * 224 + jj * 4);
                }
            }
        }
        __syncthreads();   // XP/OS reused next iter
    }
}

extern "C" void kernel_launch(void* const* d_in, const int* in_sizes, int n_in,
                              void* d_out, int out_size) {
    const float* x   = (const float*)d_in[0];
    const float* wq  = (const float*)d_in[1];
    const float* wk  = (const float*)d_in[2];
    const float* wv  = (const float*)d_in[3];
    const float* wfc = (const float*)d_in[4];
    const float* bfc = (const float*)d_in[5];
    float* out = (float*)d_out;

    int nsm = 148;
    cudaDeviceGetAttribute(&nsm, cudaDevAttrMultiProcessorCount, 0);

    cudaFuncSetAttribute(mha_kernel, cudaFuncAttributeMaxDynamicSharedMemorySize, SMEM_TOTAL);
    prep_kernel<<<7, 256>>>(wq, wk, wv, wfc);
    mha_kernel<<<nsm * 4, 128, SMEM_TOTAL>>>(x, bfc, out);
}